// round 2
// baseline (speedup 1.0000x reference)
#include <cuda_runtime.h>
#include <math.h>

#define BB   4
#define CCH  256
#define HH   128
#define WWID 128
#define HW   16384      // HH*WWID
#define NT   65536      // BB*HW tokens
#define HIDN 1024

// ---------------- scratch (static device globals; no allocs) ----------------
__device__ float g_xc [(size_t)NT * CCH];   // x transposed to [tok, C]
__device__ float g_n  [(size_t)NT * CCH];   // ln1 / ln2 output (reused)
__device__ float g_q  [(size_t)NT * CCH];   // q, later reused as y2 (fc2 out)
__device__ float g_k  [(size_t)NT * CCH];
__device__ float g_v  [(size_t)NT * CCH];
__device__ float g_x1 [(size_t)NT * CCH];   // residual-1 output
__device__ float g_hid[(size_t)NT * HIDN];  // mlp hidden

// ---------------- transpose in: x[B,C,H,W] -> xc[(b,h,w), C] ----------------
__global__ void transpose_in_kernel(const float* __restrict__ x, float* __restrict__ xc) {
    __shared__ float tile[32][33];
    int b  = blockIdx.z;
    int c0 = blockIdx.y * 32;
    int p0 = blockIdx.x * 32;     // position within HW
    int tx = threadIdx.x, ty = threadIdx.y;  // 32 x 8
#pragma unroll
    for (int j = 0; j < 32; j += 8)
        tile[ty + j][tx] = x[((size_t)b * CCH + c0 + ty + j) * HW + p0 + tx];
    __syncthreads();
#pragma unroll
    for (int j = 0; j < 32; j += 8)
        xc[((size_t)b * HW + p0 + ty + j) * CCH + c0 + tx] = tile[tx][ty + j];
}

// ---------------- layernorm over last dim (C=256), warp per token ----------------
__global__ void ln_kernel(const float* __restrict__ X, const float* __restrict__ g,
                          const float* __restrict__ b, float* __restrict__ Y) {
    int warp = threadIdx.x >> 5, lane = threadIdx.x & 31;
    size_t tok = (size_t)blockIdx.x * 4 + warp;
    const float4* x4 = (const float4*)(X + tok * CCH);
    float4 v0 = x4[lane];
    float4 v1 = x4[lane + 32];
    float s  = v0.x + v0.y + v0.z + v0.w + v1.x + v1.y + v1.z + v1.w;
    float sq = v0.x*v0.x + v0.y*v0.y + v0.z*v0.z + v0.w*v0.w
             + v1.x*v1.x + v1.y*v1.y + v1.z*v1.z + v1.w*v1.w;
#pragma unroll
    for (int off = 16; off > 0; off >>= 1) {
        s  += __shfl_xor_sync(0xffffffffu, s,  off);
        sq += __shfl_xor_sync(0xffffffffu, sq, off);
    }
    float mean = s * (1.0f / 256.0f);
    float var  = sq * (1.0f / 256.0f) - mean * mean;
    float inv  = rsqrtf(var + 1e-5f);
    const float4* g4 = (const float4*)g;
    const float4* b4 = (const float4*)b;
    float4* y4 = (float4*)(Y + tok * CCH);
    {
        float4 gg = g4[lane], bb = b4[lane], o;
        o.x = (v0.x - mean) * inv * gg.x + bb.x;
        o.y = (v0.y - mean) * inv * gg.y + bb.y;
        o.z = (v0.z - mean) * inv * gg.z + bb.z;
        o.w = (v0.w - mean) * inv * gg.w + bb.w;
        y4[lane] = o;
    }
    {
        float4 gg = g4[lane + 32], bb = b4[lane + 32], o;
        o.x = (v1.x - mean) * inv * gg.x + bb.x;
        o.y = (v1.y - mean) * inv * gg.y + bb.y;
        o.z = (v1.z - mean) * inv * gg.z + bb.z;
        o.w = (v1.w - mean) * inv * gg.w + bb.w;
        y4[lane + 32] = o;
    }
}

// ---------------- SIMT fp32 GEMM: C[M,N] = A[M,K] @ B[K,N] + bias, opt gelu ----------------
// BM=128, BN=64, BK=16, 256 threads, 8x4 per thread. M,N,K multiples of tile dims.
template <int EPI>   // 0 = none, 1 = exact gelu
__global__ void gemm_kernel(const float* __restrict__ A, const float* __restrict__ Bw,
                            const float* __restrict__ bias, float* __restrict__ Cout,
                            int K, int N) {
    __shared__ float As[16][128];
    __shared__ float Bs[16][64];
    int t  = threadIdx.x;
    int bm = blockIdx.y * 128;
    int bn = blockIdx.x * 64;
    int tm = t >> 4;          // 0..15  (8 rows each)
    int tn = t & 15;          // 0..15  (4 cols each)

    int aRow0 = t >> 2;                // rows 0..63
    int aRow1 = aRow0 + 64;            // rows 64..127
    int aK4   = (t & 3) * 4;           // k offset 0,4,8,12
    int bK    = t >> 4;                // 0..15
    int bN    = (t & 15) * 4;          // 0..60

    float acc[8][4];
#pragma unroll
    for (int i = 0; i < 8; i++)
#pragma unroll
        for (int j = 0; j < 4; j++) acc[i][j] = 0.0f;

    for (int k0 = 0; k0 < K; k0 += 16) {
        float4 a0 = *(const float4*)&A[(size_t)(bm + aRow0) * K + k0 + aK4];
        float4 a1 = *(const float4*)&A[(size_t)(bm + aRow1) * K + k0 + aK4];
        float4 b0 = *(const float4*)&Bw[(size_t)(k0 + bK) * N + bn + bN];
        As[aK4 + 0][aRow0] = a0.x; As[aK4 + 1][aRow0] = a0.y;
        As[aK4 + 2][aRow0] = a0.z; As[aK4 + 3][aRow0] = a0.w;
        As[aK4 + 0][aRow1] = a1.x; As[aK4 + 1][aRow1] = a1.y;
        As[aK4 + 2][aRow1] = a1.z; As[aK4 + 3][aRow1] = a1.w;
        *(float4*)&Bs[bK][bN] = b0;
        __syncthreads();
#pragma unroll
        for (int kk = 0; kk < 16; kk++) {
            float a[8], bfr[4];
            *(float4*)(a)     = *(float4*)&As[kk][tm * 8];
            *(float4*)(a + 4) = *(float4*)&As[kk][tm * 8 + 4];
            *(float4*)(bfr)   = *(float4*)&Bs[kk][tn * 4];
#pragma unroll
            for (int i = 0; i < 8; i++)
#pragma unroll
                for (int j = 0; j < 4; j++) acc[i][j] = fmaf(a[i], bfr[j], acc[i][j]);
        }
        __syncthreads();
    }

    float4 bv = *(const float4*)&bias[bn + tn * 4];
#pragma unroll
    for (int i = 0; i < 8; i++) {
        float4 r;
        r.x = acc[i][0] + bv.x;
        r.y = acc[i][1] + bv.y;
        r.z = acc[i][2] + bv.z;
        r.w = acc[i][3] + bv.w;
        if (EPI == 1) {
            r.x = 0.5f * r.x * (1.0f + erff(r.x * 0.70710678118654752f));
            r.y = 0.5f * r.y * (1.0f + erff(r.y * 0.70710678118654752f));
            r.z = 0.5f * r.z * (1.0f + erff(r.z * 0.70710678118654752f));
            r.w = 0.5f * r.w * (1.0f + erff(r.w * 0.70710678118654752f));
        }
        *(float4*)&Cout[(size_t)(bm + tm * 8 + i) * N + bn + tn * 4] = r;
    }
}

// ---------------- 3x3 neighborhood attention, warp per token, fused residual ----------------
__global__ void attn_kernel(const float* __restrict__ q, const float* __restrict__ k,
                            const float* __restrict__ v, const float* __restrict__ xc,
                            float* __restrict__ x1) {
    int warp = threadIdx.x >> 5, lane = threadIdx.x & 31;
    size_t tok = (size_t)blockIdx.x * 8 + warp;
    int b = (int)(tok >> 14);              // tok / HW
    int rem = (int)(tok & (HW - 1));
    int h = rem >> 7;                       // rem / W
    int w = rem & 127;

    const float4* q4 = (const float4*)(q + tok * CCH);
    float4 qa = q4[lane], qb = q4[lane + 32];

    float s[9];
#pragma unroll
    for (int n = 0; n < 9; n++) {
        int dy = n / 3 - 1, dx = n % 3 - 1;
        int hh = h + dy, ww = w + dx;
        bool valid = (hh >= 0) & (hh < HH) & (ww >= 0) & (ww < WWID);
        float part = 0.0f;
        if (valid) {
            size_t ntok = ((size_t)b * HW) + ((size_t)hh << 7) + ww;
            const float4* k4 = (const float4*)(k + ntok * CCH);
            float4 ka = k4[lane], kb = k4[lane + 32];
            part = qa.x * ka.x + qa.y * ka.y + qa.z * ka.z + qa.w * ka.w
                 + qb.x * kb.x + qb.y * kb.y + qb.z * kb.z + qb.w * kb.w;
        }
#pragma unroll
        for (int off = 16; off > 0; off >>= 1)
            part += __shfl_xor_sync(0xffffffffu, part, off);
        s[n] = valid ? part * 0.0625f : -1e30f;   // 1/sqrt(256)
    }

    float m = s[0];
#pragma unroll
    for (int n = 1; n < 9; n++) m = fmaxf(m, s[n]);
    float e[9], sum = 0.0f;
#pragma unroll
    for (int n = 0; n < 9; n++) { e[n] = (s[n] > -1e29f) ? expf(s[n] - m) : 0.0f; sum += e[n]; }
    float inv = 1.0f / sum;

    float4 acca = {0, 0, 0, 0}, accb = {0, 0, 0, 0};
#pragma unroll
    for (int n = 0; n < 9; n++) {
        if (e[n] > 0.0f) {
            float wn = e[n] * inv;
            int dy = n / 3 - 1, dx = n % 3 - 1;
            size_t ntok = ((size_t)b * HW) + ((size_t)(h + dy) << 7) + (w + dx);
            const float4* v4 = (const float4*)(v + ntok * CCH);
            float4 va = v4[lane], vb = v4[lane + 32];
            acca.x += wn * va.x; acca.y += wn * va.y; acca.z += wn * va.z; acca.w += wn * va.w;
            accb.x += wn * vb.x; accb.y += wn * vb.y; accb.z += wn * vb.z; accb.w += wn * vb.w;
        }
    }

    const float4* xc4 = (const float4*)(xc + tok * CCH);
    float4* o4 = (float4*)(x1 + tok * CCH);
    float4 ra = xc4[lane], rb = xc4[lane + 32];
    ra.x += acca.x; ra.y += acca.y; ra.z += acca.z; ra.w += acca.w;
    rb.x += accb.x; rb.y += accb.y; rb.z += accb.z; rb.w += accb.w;
    o4[lane] = ra;
    o4[lane + 32] = rb;
}

// ---------------- final: out[b,c,h,w] = x1 + y2 (transposed back) ----------------
__global__ void transpose_out_kernel(const float* __restrict__ x1, const float* __restrict__ y2,
                                     float* __restrict__ out) {
    __shared__ float tile[32][33];
    int b  = blockIdx.z;
    int c0 = blockIdx.y * 32;
    int p0 = blockIdx.x * 32;
    int tx = threadIdx.x, ty = threadIdx.y;
#pragma unroll
    for (int j = 0; j < 32; j += 8) {
        size_t idx = ((size_t)b * HW + p0 + ty + j) * CCH + c0 + tx;
        tile[ty + j][tx] = x1[idx] + y2[idx];
    }
    __syncthreads();
#pragma unroll
    for (int j = 0; j < 32; j += 8)
        out[((size_t)b * CCH + c0 + ty + j) * HW + p0 + tx] = tile[tx][ty + j];
}

// ---------------- launch ----------------
extern "C" void kernel_launch(void* const* d_in, const int* in_sizes, int n_in,
                              void* d_out, int out_size) {
    const float* x     = (const float*)d_in[0];
    const float* wq    = (const float*)d_in[1];
    const float* bq    = (const float*)d_in[2];
    const float* wk    = (const float*)d_in[3];
    const float* bk    = (const float*)d_in[4];
    const float* wv    = (const float*)d_in[5];
    const float* bv    = (const float*)d_in[6];
    const float* ln1_g = (const float*)d_in[7];
    const float* ln1_b = (const float*)d_in[8];
    const float* ln2_g = (const float*)d_in[9];
    const float* ln2_b = (const float*)d_in[10];
    const float* fc1_w = (const float*)d_in[11];
    const float* fc1_b = (const float*)d_in[12];
    const float* fc2_w = (const float*)d_in[13];
    const float* fc2_b = (const float*)d_in[14];
    float* out = (float*)d_out;

    float *xc, *nbuf, *q, *k, *v, *x1, *hid;
    cudaGetSymbolAddress((void**)&xc,  g_xc);
    cudaGetSymbolAddress((void**)&nbuf, g_n);
    cudaGetSymbolAddress((void**)&q,   g_q);
    cudaGetSymbolAddress((void**)&k,   g_k);
    cudaGetSymbolAddress((void**)&v,   g_v);
    cudaGetSymbolAddress((void**)&x1,  g_x1);
    cudaGetSymbolAddress((void**)&hid, g_hid);

    dim3 tpos(32, 8);
    transpose_in_kernel<<<dim3(HW / 32, CCH / 32, BB), tpos>>>(x, xc);
    ln_kernel<<<NT / 4, 128>>>(xc, ln1_g, ln1_b, nbuf);
    gemm_kernel<0><<<dim3(256 / 64,  NT / 128), 256>>>(nbuf, wq, bq, q, 256, 256);
    gemm_kernel<0><<<dim3(256 / 64,  NT / 128), 256>>>(nbuf, wk, bk, k, 256, 256);
    gemm_kernel<0><<<dim3(256 / 64,  NT / 128), 256>>>(nbuf, wv, bv, v, 256, 256);
    attn_kernel<<<NT / 8, 256>>>(q, k, v, xc, x1);
    ln_kernel<<<NT / 4, 128>>>(x1, ln2_g, ln2_b, nbuf);
    gemm_kernel<1><<<dim3(HIDN / 64, NT / 128), 256>>>(nbuf, fc1_w, fc1_b, hid, 256, HIDN);
    gemm_kernel<0><<<dim3(256 / 64,  NT / 128), 256>>>(hid, fc2_w, fc2_b, q /*y2*/, HIDN, 256);
    transpose_out_kernel<<<dim3(HW / 32, CCH / 32, BB), tpos>>>(x1, q, out);
}

// round 4
// speedup vs baseline: 2.4958x; 2.4958x over previous
#include <cuda_runtime.h>
#include <math.h>

#define BB   4
#define CCH  256
#define HH   128
#define WWID 128
#define HW   16384      // HH*WWID
#define NT   65536      // BB*HW tokens
#define HIDN 1024

// ---------------- scratch (static device globals; no allocs) ----------------
__device__ float g_xc [(size_t)NT * CCH];   // x transposed to [tok, C]
__device__ float g_n  [(size_t)NT * CCH];   // ln1 / ln2 output (reused)
__device__ float g_q  [(size_t)NT * CCH];   // q, later reused as y2 (fc2 out)
__device__ float g_k  [(size_t)NT * CCH];
__device__ float g_v  [(size_t)NT * CCH];
__device__ float g_x1 [(size_t)NT * CCH];   // residual-1 output
__device__ float g_hid[(size_t)NT * HIDN];  // mlp hidden

// ---------------- transpose in: x[B,C,H,W] -> xc[(b,h,w), C] ----------------
__global__ void transpose_in_kernel(const float* __restrict__ x, float* __restrict__ xc) {
    __shared__ float tile[32][33];
    int b  = blockIdx.z;
    int c0 = blockIdx.y * 32;
    int p0 = blockIdx.x * 32;     // position within HW
    int tx = threadIdx.x, ty = threadIdx.y;  // 32 x 8
#pragma unroll
    for (int j = 0; j < 32; j += 8)
        tile[ty + j][tx] = x[((size_t)b * CCH + c0 + ty + j) * HW + p0 + tx];
    __syncthreads();
#pragma unroll
    for (int j = 0; j < 32; j += 8)
        xc[((size_t)b * HW + p0 + ty + j) * CCH + c0 + tx] = tile[tx][ty + j];
}

// ---------------- layernorm over last dim (C=256), warp per token ----------------
__global__ void ln_kernel(const float* __restrict__ X, const float* __restrict__ g,
                          const float* __restrict__ b, float* __restrict__ Y) {
    int warp = threadIdx.x >> 5, lane = threadIdx.x & 31;
    size_t tok = (size_t)blockIdx.x * 4 + warp;
    const float4* x4 = (const float4*)(X + tok * CCH);
    float4 v0 = x4[lane];
    float4 v1 = x4[lane + 32];
    float s  = v0.x + v0.y + v0.z + v0.w + v1.x + v1.y + v1.z + v1.w;
    float sq = v0.x*v0.x + v0.y*v0.y + v0.z*v0.z + v0.w*v0.w
             + v1.x*v1.x + v1.y*v1.y + v1.z*v1.z + v1.w*v1.w;
#pragma unroll
    for (int off = 16; off > 0; off >>= 1) {
        s  += __shfl_xor_sync(0xffffffffu, s,  off);
        sq += __shfl_xor_sync(0xffffffffu, sq, off);
    }
    float mean = s * (1.0f / 256.0f);
    float var  = sq * (1.0f / 256.0f) - mean * mean;
    float inv  = rsqrtf(var + 1e-5f);
    const float4* g4 = (const float4*)g;
    const float4* b4 = (const float4*)b;
    float4* y4 = (float4*)(Y + tok * CCH);
    {
        float4 gg = g4[lane], bb = b4[lane], o;
        o.x = (v0.x - mean) * inv * gg.x + bb.x;
        o.y = (v0.y - mean) * inv * gg.y + bb.y;
        o.z = (v0.z - mean) * inv * gg.z + bb.z;
        o.w = (v0.w - mean) * inv * gg.w + bb.w;
        y4[lane] = o;
    }
    {
        float4 gg = g4[lane + 32], bb = b4[lane + 32], o;
        o.x = (v1.x - mean) * inv * gg.x + bb.x;
        o.y = (v1.y - mean) * inv * gg.y + bb.y;
        o.z = (v1.z - mean) * inv * gg.z + bb.z;
        o.w = (v1.w - mean) * inv * gg.w + bb.w;
        y4[lane + 32] = o;
    }
}

// ---------------- tf32 tensor-core GEMM ----------------
// C[M,N] = A[M,K] @ B[K,N] + bias, optional exact gelu.
// BM=128, BN=128, BK=32; 256 threads = 8 warps, warp tile 32x64 (2x8 m16n8k8 frags).
__device__ __forceinline__ unsigned f2tf32(float x) {
    unsigned u;
    asm("cvt.rna.tf32.f32 %0, %1;" : "=r"(u) : "f"(x));
    return u;
}

#define AS_STRIDE 36
#define BS_STRIDE 136

template <int EPI>   // 0 = none, 1 = exact gelu
__global__ void __launch_bounds__(256)
gemm_tf32_kernel(const float* __restrict__ A, const float* __restrict__ Bw,
                 const float* __restrict__ bias, float* __restrict__ Cout,
                 int K, int N) {
    __shared__ float As[128][AS_STRIDE];   // [m][k], stride 36 -> conflict-free frag loads
    __shared__ float Bs[32][BS_STRIDE];    // [k][n], stride 136 -> conflict-free frag loads

    int t    = threadIdx.x;
    int warp = t >> 5, lane = t & 31;
    int g    = lane >> 2;       // group 0..7
    int tig  = lane & 3;        // thread-in-group 0..3
    int wm   = (warp >> 1) * 32;  // warp row offset   (4 warps in M)
    int wn   = (warp & 1) * 64;   // warp col offset   (2 warps in N)
    int bm   = blockIdx.y * 128;
    int bn   = blockIdx.x * 128;

    float c[2][8][4];
#pragma unroll
    for (int mf = 0; mf < 2; mf++)
#pragma unroll
        for (int nf = 0; nf < 8; nf++)
#pragma unroll
            for (int j = 0; j < 4; j++) c[mf][nf][j] = 0.0f;

    for (int kb = 0; kb < K; kb += 32) {
        // stage A tile 128x32 (cvt to tf32)
#pragma unroll
        for (int i = 0; i < 4; i++) {
            int f   = t + 256 * i;
            int row = f >> 3;
            int c4  = (f & 7) * 4;
            float4 av = *(const float4*)&A[(size_t)(bm + row) * K + kb + c4];
            float* dst = &As[row][c4];
            dst[0] = __uint_as_float(f2tf32(av.x));
            dst[1] = __uint_as_float(f2tf32(av.y));
            dst[2] = __uint_as_float(f2tf32(av.z));
            dst[3] = __uint_as_float(f2tf32(av.w));
        }
        // stage B tile 32x128
#pragma unroll
        for (int i = 0; i < 4; i++) {
            int f   = t + 256 * i;
            int row = f >> 5;
            int c4  = (f & 31) * 4;
            float4 bv = *(const float4*)&Bw[(size_t)(kb + row) * N + bn + c4];
            float* dst = &Bs[row][c4];
            dst[0] = __uint_as_float(f2tf32(bv.x));
            dst[1] = __uint_as_float(f2tf32(bv.y));
            dst[2] = __uint_as_float(f2tf32(bv.z));
            dst[3] = __uint_as_float(f2tf32(bv.w));
        }
        __syncthreads();

#pragma unroll
        for (int ks = 0; ks < 4; ks++) {
            int k0 = ks * 8;
            unsigned a[2][4];
#pragma unroll
            for (int mf = 0; mf < 2; mf++) {
                int r0 = wm + mf * 16 + g;
                a[mf][0] = __float_as_uint(As[r0    ][k0 + tig]);
                a[mf][1] = __float_as_uint(As[r0 + 8][k0 + tig]);
                a[mf][2] = __float_as_uint(As[r0    ][k0 + tig + 4]);
                a[mf][3] = __float_as_uint(As[r0 + 8][k0 + tig + 4]);
            }
            unsigned b[8][2];
#pragma unroll
            for (int nf = 0; nf < 8; nf++) {
                int col = wn + nf * 8 + g;
                b[nf][0] = __float_as_uint(Bs[k0 + tig    ][col]);
                b[nf][1] = __float_as_uint(Bs[k0 + tig + 4][col]);
            }
#pragma unroll
            for (int mf = 0; mf < 2; mf++)
#pragma unroll
                for (int nf = 0; nf < 8; nf++) {
                    asm volatile(
                        "mma.sync.aligned.m16n8k8.row.col.f32.tf32.tf32.f32 "
                        "{%0,%1,%2,%3}, {%4,%5,%6,%7}, {%8,%9}, {%0,%1,%2,%3};"
                        : "+f"(c[mf][nf][0]), "+f"(c[mf][nf][1]),
                          "+f"(c[mf][nf][2]), "+f"(c[mf][nf][3])
                        : "r"(a[mf][0]), "r"(a[mf][1]), "r"(a[mf][2]), "r"(a[mf][3]),
                          "r"(b[nf][0]), "r"(b[nf][1]));
                }
        }
        __syncthreads();
    }

    // epilogue: bias (+gelu) and store
#pragma unroll
    for (int mf = 0; mf < 2; mf++) {
        int row0 = bm + wm + mf * 16 + g;
#pragma unroll
        for (int nf = 0; nf < 8; nf++) {
            int col = bn + wn + nf * 8 + 2 * tig;
            float b0 = bias[col], b1 = bias[col + 1];
            float v0 = c[mf][nf][0] + b0;
            float v1 = c[mf][nf][1] + b1;
            float v2 = c[mf][nf][2] + b0;
            float v3 = c[mf][nf][3] + b1;
            if (EPI == 1) {
                v0 = 0.5f * v0 * (1.0f + erff(v0 * 0.70710678118654752f));
                v1 = 0.5f * v1 * (1.0f + erff(v1 * 0.70710678118654752f));
                v2 = 0.5f * v2 * (1.0f + erff(v2 * 0.70710678118654752f));
                v3 = 0.5f * v3 * (1.0f + erff(v3 * 0.70710678118654752f));
            }
            *(float2*)&Cout[(size_t)row0 * N + col]       = make_float2(v0, v1);
            *(float2*)&Cout[(size_t)(row0 + 8) * N + col] = make_float2(v2, v3);
        }
    }
}

// ---------------- 3x3 neighborhood attention, warp per token, fused residual ----------------
__global__ void attn_kernel(const float* __restrict__ q, const float* __restrict__ k,
                            const float* __restrict__ v, const float* __restrict__ xc,
                            float* __restrict__ x1) {
    int warp = threadIdx.x >> 5, lane = threadIdx.x & 31;
    size_t tok = (size_t)blockIdx.x * 8 + warp;
    int b = (int)(tok >> 14);
    int rem = (int)(tok & (HW - 1));
    int h = rem >> 7;
    int w = rem & 127;

    const float4* q4 = (const float4*)(q + tok * CCH);
    float4 qa = q4[lane], qb = q4[lane + 32];

    float s[9];
#pragma unroll
    for (int n = 0; n < 9; n++) {
        int dy = n / 3 - 1, dx = n % 3 - 1;
        int hh = h + dy, ww = w + dx;
        bool valid = (hh >= 0) & (hh < HH) & (ww >= 0) & (ww < WWID);
        float part = 0.0f;
        if (valid) {
            size_t ntok = ((size_t)b * HW) + ((size_t)hh << 7) + ww;
            const float4* k4 = (const float4*)(k + ntok * CCH);
            float4 ka = k4[lane], kb = k4[lane + 32];
            part = qa.x * ka.x + qa.y * ka.y + qa.z * ka.z + qa.w * ka.w
                 + qb.x * kb.x + qb.y * kb.y + qb.z * kb.z + qb.w * kb.w;
        }
#pragma unroll
        for (int off = 16; off > 0; off >>= 1)
            part += __shfl_xor_sync(0xffffffffu, part, off);
        s[n] = valid ? part * 0.0625f : -1e30f;   // 1/sqrt(256)
    }

    float m = s[0];
#pragma unroll
    for (int n = 1; n < 9; n++) m = fmaxf(m, s[n]);
    float e[9], sum = 0.0f;
#pragma unroll
    for (int n = 0; n < 9; n++) { e[n] = (s[n] > -1e29f) ? expf(s[n] - m) : 0.0f; sum += e[n]; }
    float inv = 1.0f / sum;

    float4 acca = {0, 0, 0, 0}, accb = {0, 0, 0, 0};
#pragma unroll
    for (int n = 0; n < 9; n++) {
        if (e[n] > 0.0f) {
            float wn = e[n] * inv;
            int dy = n / 3 - 1, dx = n % 3 - 1;
            size_t ntok = ((size_t)b * HW) + ((size_t)(h + dy) << 7) + (w + dx);
            const float4* v4 = (const float4*)(v + ntok * CCH);
            float4 va = v4[lane], vb = v4[lane + 32];
            acca.x += wn * va.x; acca.y += wn * va.y; acca.z += wn * va.z; acca.w += wn * va.w;
            accb.x += wn * vb.x; accb.y += wn * vb.y; accb.z += wn * vb.z; accb.w += wn * vb.w;
        }
    }

    const float4* xc4 = (const float4*)(xc + tok * CCH);
    float4* o4 = (float4*)(x1 + tok * CCH);
    float4 ra = xc4[lane], rb = xc4[lane + 32];
    ra.x += acca.x; ra.y += acca.y; ra.z += acca.z; ra.w += acca.w;
    rb.x += accb.x; rb.y += accb.y; rb.z += accb.z; rb.w += accb.w;
    o4[lane] = ra;
    o4[lane + 32] = rb;
}

// ---------------- final: out[b,c,h,w] = x1 + y2 (transposed back) ----------------
__global__ void transpose_out_kernel(const float* __restrict__ x1, const float* __restrict__ y2,
                                     float* __restrict__ out) {
    __shared__ float tile[32][33];
    int b  = blockIdx.z;
    int c0 = blockIdx.y * 32;
    int p0 = blockIdx.x * 32;
    int tx = threadIdx.x, ty = threadIdx.y;
#pragma unroll
    for (int j = 0; j < 32; j += 8) {
        size_t idx = ((size_t)b * HW + p0 + ty + j) * CCH + c0 + tx;
        tile[ty + j][tx] = x1[idx] + y2[idx];
    }
    __syncthreads();
#pragma unroll
    for (int j = 0; j < 32; j += 8)
        out[((size_t)b * CCH + c0 + ty + j) * HW + p0 + tx] = tile[tx][ty + j];
}

// ---------------- launch ----------------
extern "C" void kernel_launch(void* const* d_in, const int* in_sizes, int n_in,
                              void* d_out, int out_size) {
    const float* x     = (const float*)d_in[0];
    const float* wq    = (const float*)d_in[1];
    const float* bq    = (const float*)d_in[2];
    const float* wk    = (const float*)d_in[3];
    const float* bk    = (const float*)d_in[4];
    const float* wv    = (const float*)d_in[5];
    const float* bv    = (const float*)d_in[6];
    const float* ln1_g = (const float*)d_in[7];
    const float* ln1_b = (const float*)d_in[8];
    const float* ln2_g = (const float*)d_in[9];
    const float* ln2_b = (const float*)d_in[10];
    const float* fc1_w = (const float*)d_in[11];
    const float* fc1_b = (const float*)d_in[12];
    const float* fc2_w = (const float*)d_in[13];
    const float* fc2_b = (const float*)d_in[14];
    float* out = (float*)d_out;

    float *xc, *nbuf, *q, *k, *v, *x1, *hid;
    cudaGetSymbolAddress((void**)&xc,  g_xc);
    cudaGetSymbolAddress((void**)&nbuf, g_n);
    cudaGetSymbolAddress((void**)&q,   g_q);
    cudaGetSymbolAddress((void**)&k,   g_k);
    cudaGetSymbolAddress((void**)&v,   g_v);
    cudaGetSymbolAddress((void**)&x1,  g_x1);
    cudaGetSymbolAddress((void**)&hid, g_hid);

    dim3 tpos(32, 8);
    transpose_in_kernel<<<dim3(HW / 32, CCH / 32, BB), tpos>>>(x, xc);
    ln_kernel<<<NT / 4, 128>>>(xc, ln1_g, ln1_b, nbuf);
    gemm_tf32_kernel<0><<<dim3(256 / 128,  NT / 128), 256>>>(nbuf, wq, bq, q, 256, 256);
    gemm_tf32_kernel<0><<<dim3(256 / 128,  NT / 128), 256>>>(nbuf, wk, bk, k, 256, 256);
    gemm_tf32_kernel<0><<<dim3(256 / 128,  NT / 128), 256>>>(nbuf, wv, bv, v, 256, 256);
    attn_kernel<<<NT / 8, 256>>>(q, k, v, xc, x1);
    ln_kernel<<<NT / 4, 128>>>(x1, ln2_g, ln2_b, nbuf);
    gemm_tf32_kernel<1><<<dim3(HIDN / 128, NT / 128), 256>>>(nbuf, fc1_w, fc1_b, hid, 256, HIDN);
    gemm_tf32_kernel<0><<<dim3(256 / 128,  NT / 128), 256>>>(hid, fc2_w, fc2_b, q /*y2*/, HIDN, 256);
    transpose_out_kernel<<<dim3(HW / 32, CCH / 32, BB), tpos>>>(x1, q, out);
}

// round 5
// speedup vs baseline: 2.9622x; 1.1869x over previous
#include <cuda_runtime.h>
#include <math.h>

#define BB   4
#define CCH  256
#define HH   128
#define WWID 128
#define HW   16384      // HH*WWID
#define NT   65536      // BB*HW tokens
#define HIDN 1024

// ---------------- scratch (static device globals; no allocs) ----------------
__device__ float g_xc [(size_t)NT * CCH];   // x transposed to [tok, C]
__device__ float g_n  [(size_t)NT * CCH];   // ln1 / ln2 output (tf32-rounded)
__device__ float g_q  [(size_t)NT * CCH];   // q, later reused as y2 (fc2 out)
__device__ float g_k  [(size_t)NT * CCH];
__device__ float g_v  [(size_t)NT * CCH];
__device__ float g_x1 [(size_t)NT * CCH];   // residual-1 output
__device__ float g_hid[(size_t)NT * HIDN];  // mlp hidden (tf32-rounded)
__device__ float g_w  [720896];             // tf32-rounded weights: wq,wk,wv,fc1,fc2

#define WOFF_Q   0
#define WOFF_K   65536
#define WOFF_V   131072
#define WOFF_FC1 196608
#define WOFF_FC2 458752

__device__ __forceinline__ unsigned f2tf32(float x) {
    unsigned u;
    asm("cvt.rna.tf32.f32 %0, %1;" : "=r"(u) : "f"(x));
    return u;
}
__device__ __forceinline__ float rtf32(float x) { return __uint_as_float(f2tf32(x)); }

// ---------------- weight tf32 pre-round ----------------
__global__ void round_copy_kernel(const float* __restrict__ src, float* __restrict__ dst, int n) {
    int i = (blockIdx.x * 256 + threadIdx.x) * 4;
    if (i < n) {
        float4 v = *(const float4*)&src[i];
        v.x = rtf32(v.x); v.y = rtf32(v.y); v.z = rtf32(v.z); v.w = rtf32(v.w);
        *(float4*)&dst[i] = v;
    }
}

// ---------------- transpose in: x[B,C,H,W] -> xc[(b,h,w), C] ----------------
__global__ void transpose_in_kernel(const float* __restrict__ x, float* __restrict__ xc) {
    __shared__ float tile[32][33];
    int b  = blockIdx.z;
    int c0 = blockIdx.y * 32;
    int p0 = blockIdx.x * 32;
    int tx = threadIdx.x, ty = threadIdx.y;  // 32 x 8
#pragma unroll
    for (int j = 0; j < 32; j += 8)
        tile[ty + j][tx] = x[((size_t)b * CCH + c0 + ty + j) * HW + p0 + tx];
    __syncthreads();
#pragma unroll
    for (int j = 0; j < 32; j += 8)
        xc[((size_t)b * HW + p0 + ty + j) * CCH + c0 + tx] = tile[tx][ty + j];
}

// ---------------- layernorm (C=256), warp per token; tf32-rounded output ----------------
__global__ void ln_kernel(const float* __restrict__ X, const float* __restrict__ g,
                          const float* __restrict__ b, float* __restrict__ Y) {
    int warp = threadIdx.x >> 5, lane = threadIdx.x & 31;
    size_t tok = (size_t)blockIdx.x * 4 + warp;
    const float4* x4 = (const float4*)(X + tok * CCH);
    float4 v0 = x4[lane];
    float4 v1 = x4[lane + 32];
    float s  = v0.x + v0.y + v0.z + v0.w + v1.x + v1.y + v1.z + v1.w;
    float sq = v0.x*v0.x + v0.y*v0.y + v0.z*v0.z + v0.w*v0.w
             + v1.x*v1.x + v1.y*v1.y + v1.z*v1.z + v1.w*v1.w;
#pragma unroll
    for (int off = 16; off > 0; off >>= 1) {
        s  += __shfl_xor_sync(0xffffffffu, s,  off);
        sq += __shfl_xor_sync(0xffffffffu, sq, off);
    }
    float mean = s * (1.0f / 256.0f);
    float var  = sq * (1.0f / 256.0f) - mean * mean;
    float inv  = rsqrtf(var + 1e-5f);
    const float4* g4 = (const float4*)g;
    const float4* b4 = (const float4*)b;
    float4* y4 = (float4*)(Y + tok * CCH);
    {
        float4 gg = g4[lane], bb = b4[lane], o;
        o.x = rtf32((v0.x - mean) * inv * gg.x + bb.x);
        o.y = rtf32((v0.y - mean) * inv * gg.y + bb.y);
        o.z = rtf32((v0.z - mean) * inv * gg.z + bb.z);
        o.w = rtf32((v0.w - mean) * inv * gg.w + bb.w);
        y4[lane] = o;
    }
    {
        float4 gg = g4[lane + 32], bb = b4[lane + 32], o;
        o.x = rtf32((v1.x - mean) * inv * gg.x + bb.x);
        o.y = rtf32((v1.y - mean) * inv * gg.y + bb.y);
        o.z = rtf32((v1.z - mean) * inv * gg.z + bb.z);
        o.w = rtf32((v1.w - mean) * inv * gg.w + bb.w);
        y4[lane + 32] = o;
    }
}

// ---------------- 3-stage cp.async tf32 tensor-core GEMM ----------------
// C[M,N] = A[M,K] @ B[K,N] + bias. Inputs must already be tf32-rounded values.
// BM=128, BN=128, BK=32; 256 threads = 8 warps, warp tile 32x64 (2x8 m16n8k8).
#define AS_STRIDE 36
#define BS_STRIDE 136
#define A_STAGE (128 * AS_STRIDE)          // 4608 floats
#define B_STAGE (32 * BS_STRIDE)           // 4352 floats
#define STAGE_F (A_STAGE + B_STAGE)        // 8960 floats
#define NSTAGE  3
#define GEMM_SMEM_BYTES (NSTAGE * STAGE_F * 4)   // 107520 B

__device__ __forceinline__ void cp16(float* dst, const float* src) {
    unsigned d = (unsigned)__cvta_generic_to_shared(dst);
    asm volatile("cp.async.cg.shared.global [%0], [%1], 16;" :: "r"(d), "l"(src));
}

template <int EPI>   // 0 = none, 1 = exact gelu + tf32-round (for hid)
__global__ void __launch_bounds__(256)
gemm_tf32_kernel(const float* __restrict__ A, const float* __restrict__ Bw,
                 const float* __restrict__ bias, float* __restrict__ Cout,
                 int K, int N) {
    extern __shared__ float sm[];
    int t    = threadIdx.x;
    int warp = t >> 5, lane = t & 31;
    int g    = lane >> 2;
    int tig  = lane & 3;
    int wm   = (warp >> 1) * 32;
    int wn   = (warp & 1) * 64;
    int bm   = blockIdx.y * 128;
    int bn   = blockIdx.x * 128;

    // per-thread staging coordinates
    int aRow = t >> 3;            // 0..31 (plus +32*i)
    int aC4  = (t & 7) * 4;       // k offset 0..28
    int bRow = t >> 5;            // 0..7 (plus +8*i)
    int bC4  = (t & 31) * 4;      // n offset 0..124

    int nK = K >> 5;

    // prefetch stage s with k-block kb
    auto prefetch = [&](int s, int kb) {
        float* As = sm + s * STAGE_F;
        float* Bs = As + A_STAGE;
#pragma unroll
        for (int i = 0; i < 4; i++) {
            int row = aRow + 32 * i;
            cp16(&As[row * AS_STRIDE + aC4], &A[(size_t)(bm + row) * K + kb + aC4]);
        }
#pragma unroll
        for (int i = 0; i < 4; i++) {
            int row = bRow + 8 * i;
            cp16(&Bs[row * BS_STRIDE + bC4], &Bw[(size_t)(kb + row) * N + bn + bC4]);
        }
    };

    float c[2][8][4];
#pragma unroll
    for (int mf = 0; mf < 2; mf++)
#pragma unroll
        for (int nf = 0; nf < 8; nf++)
#pragma unroll
            for (int j = 0; j < 4; j++) c[mf][nf][j] = 0.0f;

    prefetch(0, 0);
    asm volatile("cp.async.commit_group;");
    prefetch(1, 32);
    asm volatile("cp.async.commit_group;");

    for (int kb = 0; kb < nK; kb++) {
        asm volatile("cp.async.wait_group 1;");
        __syncthreads();

        // prefetch 2 ahead into the stage computed 1 iter ago (sync above protects it)
        if (kb + 2 < nK) prefetch((kb + 2) % NSTAGE, (kb + 2) << 5);
        asm volatile("cp.async.commit_group;");

        const float* As = sm + (kb % NSTAGE) * STAGE_F;
        const float* Bs = As + A_STAGE;

#pragma unroll
        for (int ks = 0; ks < 4; ks++) {
            int k0 = ks * 8;
            unsigned a[2][4];
#pragma unroll
            for (int mf = 0; mf < 2; mf++) {
                int r0 = wm + mf * 16 + g;
                a[mf][0] = __float_as_uint(As[r0 * AS_STRIDE + k0 + tig]);
                a[mf][1] = __float_as_uint(As[(r0 + 8) * AS_STRIDE + k0 + tig]);
                a[mf][2] = __float_as_uint(As[r0 * AS_STRIDE + k0 + tig + 4]);
                a[mf][3] = __float_as_uint(As[(r0 + 8) * AS_STRIDE + k0 + tig + 4]);
            }
            unsigned b[8][2];
#pragma unroll
            for (int nf = 0; nf < 8; nf++) {
                int col = wn + nf * 8 + g;
                b[nf][0] = __float_as_uint(Bs[(k0 + tig) * BS_STRIDE + col]);
                b[nf][1] = __float_as_uint(Bs[(k0 + tig + 4) * BS_STRIDE + col]);
            }
#pragma unroll
            for (int mf = 0; mf < 2; mf++)
#pragma unroll
                for (int nf = 0; nf < 8; nf++) {
                    asm volatile(
                        "mma.sync.aligned.m16n8k8.row.col.f32.tf32.tf32.f32 "
                        "{%0,%1,%2,%3}, {%4,%5,%6,%7}, {%8,%9}, {%0,%1,%2,%3};"
                        : "+f"(c[mf][nf][0]), "+f"(c[mf][nf][1]),
                          "+f"(c[mf][nf][2]), "+f"(c[mf][nf][3])
                        : "r"(a[mf][0]), "r"(a[mf][1]), "r"(a[mf][2]), "r"(a[mf][3]),
                          "r"(b[nf][0]), "r"(b[nf][1]));
                }
        }
    }

    // epilogue: bias (+gelu) and store
#pragma unroll
    for (int mf = 0; mf < 2; mf++) {
        int row0 = bm + wm + mf * 16 + g;
#pragma unroll
        for (int nf = 0; nf < 8; nf++) {
            int col = bn + wn + nf * 8 + 2 * tig;
            float b0 = bias[col], b1 = bias[col + 1];
            float v0 = c[mf][nf][0] + b0;
            float v1 = c[mf][nf][1] + b1;
            float v2 = c[mf][nf][2] + b0;
            float v3 = c[mf][nf][3] + b1;
            if (EPI == 1) {
                v0 = rtf32(0.5f * v0 * (1.0f + erff(v0 * 0.70710678118654752f)));
                v1 = rtf32(0.5f * v1 * (1.0f + erff(v1 * 0.70710678118654752f)));
                v2 = rtf32(0.5f * v2 * (1.0f + erff(v2 * 0.70710678118654752f)));
                v3 = rtf32(0.5f * v3 * (1.0f + erff(v3 * 0.70710678118654752f)));
            }
            *(float2*)&Cout[(size_t)row0 * N + col]       = make_float2(v0, v1);
            *(float2*)&Cout[(size_t)(row0 + 8) * N + col] = make_float2(v2, v3);
        }
    }
}

// ---------------- 3x3 neighborhood attention, warp per token, fused residual ----------------
__global__ void attn_kernel(const float* __restrict__ q, const float* __restrict__ k,
                            const float* __restrict__ v, const float* __restrict__ xc,
                            float* __restrict__ x1) {
    int warp = threadIdx.x >> 5, lane = threadIdx.x & 31;
    size_t tok = (size_t)blockIdx.x * 8 + warp;
    int b = (int)(tok >> 14);
    int rem = (int)(tok & (HW - 1));
    int h = rem >> 7;
    int w = rem & 127;

    const float4* q4 = (const float4*)(q + tok * CCH);
    float4 qa = q4[lane], qb = q4[lane + 32];

    float s[9];
#pragma unroll
    for (int n = 0; n < 9; n++) {
        int dy = n / 3 - 1, dx = n % 3 - 1;
        int hh = h + dy, ww = w + dx;
        bool valid = (hh >= 0) & (hh < HH) & (ww >= 0) & (ww < WWID);
        float part = 0.0f;
        if (valid) {
            size_t ntok = ((size_t)b * HW) + ((size_t)hh << 7) + ww;
            const float4* k4 = (const float4*)(k + ntok * CCH);
            float4 ka = k4[lane], kb = k4[lane + 32];
            part = qa.x * ka.x + qa.y * ka.y + qa.z * ka.z + qa.w * ka.w
                 + qb.x * kb.x + qb.y * kb.y + qb.z * kb.z + qb.w * kb.w;
        }
#pragma unroll
        for (int off = 16; off > 0; off >>= 1)
            part += __shfl_xor_sync(0xffffffffu, part, off);
        s[n] = valid ? part * 0.0625f : -1e30f;   // 1/sqrt(256)
    }

    float m = s[0];
#pragma unroll
    for (int n = 1; n < 9; n++) m = fmaxf(m, s[n]);
    float e[9], sum = 0.0f;
#pragma unroll
    for (int n = 0; n < 9; n++) { e[n] = (s[n] > -1e29f) ? expf(s[n] - m) : 0.0f; sum += e[n]; }
    float inv = 1.0f / sum;

    float4 acca = {0, 0, 0, 0}, accb = {0, 0, 0, 0};
#pragma unroll
    for (int n = 0; n < 9; n++) {
        if (e[n] > 0.0f) {
            float wn = e[n] * inv;
            int dy = n / 3 - 1, dx = n % 3 - 1;
            size_t ntok = ((size_t)b * HW) + ((size_t)(h + dy) << 7) + (w + dx);
            const float4* v4 = (const float4*)(v + ntok * CCH);
            float4 va = v4[lane], vb = v4[lane + 32];
            acca.x += wn * va.x; acca.y += wn * va.y; acca.z += wn * va.z; acca.w += wn * va.w;
            accb.x += wn * vb.x; accb.y += wn * vb.y; accb.z += wn * vb.z; accb.w += wn * vb.w;
        }
    }

    const float4* xc4 = (const float4*)(xc + tok * CCH);
    float4* o4 = (float4*)(x1 + tok * CCH);
    float4 ra = xc4[lane], rb = xc4[lane + 32];
    ra.x += acca.x; ra.y += acca.y; ra.z += acca.z; ra.w += acca.w;
    rb.x += accb.x; rb.y += accb.y; rb.z += accb.z; rb.w += accb.w;
    o4[lane] = ra;
    o4[lane + 32] = rb;
}

// ---------------- final: out[b,c,h,w] = x1 + y2 (transposed back) ----------------
__global__ void transpose_out_kernel(const float* __restrict__ x1, const float* __restrict__ y2,
                                     float* __restrict__ out) {
    __shared__ float tile[32][33];
    int b  = blockIdx.z;
    int c0 = blockIdx.y * 32;
    int p0 = blockIdx.x * 32;
    int tx = threadIdx.x, ty = threadIdx.y;
#pragma unroll
    for (int j = 0; j < 32; j += 8) {
        size_t idx = ((size_t)b * HW + p0 + ty + j) * CCH + c0 + tx;
        tile[ty + j][tx] = x1[idx] + y2[idx];
    }
    __syncthreads();
#pragma unroll
    for (int j = 0; j < 32; j += 8)
        out[((size_t)b * CCH + c0 + ty + j) * HW + p0 + tx] = tile[tx][ty + j];
}

// ---------------- launch ----------------
extern "C" void kernel_launch(void* const* d_in, const int* in_sizes, int n_in,
                              void* d_out, int out_size) {
    const float* x     = (const float*)d_in[0];
    const float* wq    = (const float*)d_in[1];
    const float* bq    = (const float*)d_in[2];
    const float* wk    = (const float*)d_in[3];
    const float* bk    = (const float*)d_in[4];
    const float* wv    = (const float*)d_in[5];
    const float* bv    = (const float*)d_in[6];
    const float* ln1_g = (const float*)d_in[7];
    const float* ln1_b = (const float*)d_in[8];
    const float* ln2_g = (const float*)d_in[9];
    const float* ln2_b = (const float*)d_in[10];
    const float* fc1_w = (const float*)d_in[11];
    const float* fc1_b = (const float*)d_in[12];
    const float* fc2_w = (const float*)d_in[13];
    const float* fc2_b = (const float*)d_in[14];
    float* out = (float*)d_out;

    float *xc, *nbuf, *q, *k, *v, *x1, *hid, *wbuf;
    cudaGetSymbolAddress((void**)&xc,  g_xc);
    cudaGetSymbolAddress((void**)&nbuf, g_n);
    cudaGetSymbolAddress((void**)&q,   g_q);
    cudaGetSymbolAddress((void**)&k,   g_k);
    cudaGetSymbolAddress((void**)&v,   g_v);
    cudaGetSymbolAddress((void**)&x1,  g_x1);
    cudaGetSymbolAddress((void**)&hid, g_hid);
    cudaGetSymbolAddress((void**)&wbuf, g_w);

    cudaFuncSetAttribute(gemm_tf32_kernel<0>,
                         cudaFuncAttributeMaxDynamicSharedMemorySize, GEMM_SMEM_BYTES);
    cudaFuncSetAttribute(gemm_tf32_kernel<1>,
                         cudaFuncAttributeMaxDynamicSharedMemorySize, GEMM_SMEM_BYTES);

    // pre-round weights to tf32 (values exactly representable -> GEMM needs no cvt)
    round_copy_kernel<<<64,  256>>>(wq,    wbuf + WOFF_Q,   65536);
    round_copy_kernel<<<64,  256>>>(wk,    wbuf + WOFF_K,   65536);
    round_copy_kernel<<<64,  256>>>(wv,    wbuf + WOFF_V,   65536);
    round_copy_kernel<<<256, 256>>>(fc1_w, wbuf + WOFF_FC1, 262144);
    round_copy_kernel<<<256, 256>>>(fc2_w, wbuf + WOFF_FC2, 262144);

    dim3 tpos(32, 8);
    transpose_in_kernel<<<dim3(HW / 32, CCH / 32, BB), tpos>>>(x, xc);
    ln_kernel<<<NT / 4, 128>>>(xc, ln1_g, ln1_b, nbuf);
    gemm_tf32_kernel<0><<<dim3(2, NT / 128), 256, GEMM_SMEM_BYTES>>>(nbuf, wbuf + WOFF_Q, bq, q, 256, 256);
    gemm_tf32_kernel<0><<<dim3(2, NT / 128), 256, GEMM_SMEM_BYTES>>>(nbuf, wbuf + WOFF_K, bk, k, 256, 256);
    gemm_tf32_kernel<0><<<dim3(2, NT / 128), 256, GEMM_SMEM_BYTES>>>(nbuf, wbuf + WOFF_V, bv, v, 256, 256);
    attn_kernel<<<NT / 8, 256>>>(q, k, v, xc, x1);
    ln_kernel<<<NT / 4, 128>>>(x1, ln2_g, ln2_b, nbuf);
    gemm_tf32_kernel<1><<<dim3(8, NT / 128), 256, GEMM_SMEM_BYTES>>>(nbuf, wbuf + WOFF_FC1, fc1_b, hid, 256, HIDN);
    gemm_tf32_kernel<0><<<dim3(2, NT / 128), 256, GEMM_SMEM_BYTES>>>(hid, wbuf + WOFF_FC2, fc2_b, q /*y2*/, HIDN, 256);
    transpose_out_kernel<<<dim3(HW / 32, CCH / 32, BB), tpos>>>(x1, q, out);
}

// round 6
// speedup vs baseline: 3.0254x; 1.0213x over previous
#include <cuda_runtime.h>
#include <math.h>

#define BB   4
#define CCH  256
#define HH   128
#define WWID 128
#define HW   16384      // HH*WWID
#define NT   65536      // BB*HW tokens
#define HIDN 1024
#define NQKV 768

// ---------------- scratch (static device globals; no allocs) ----------------
__device__ float g_xc  [(size_t)NT * CCH];    // x transposed to [tok, C]
__device__ float g_n   [(size_t)NT * CCH];    // ln1 / ln2 output (tf32-rounded)
__device__ float g_qkv [(size_t)NT * NQKV];   // q|k|v packed per token
__device__ float g_x1  [(size_t)NT * CCH];    // residual-1 output
__device__ float g_hid [(size_t)NT * HIDN];   // mlp hidden (tf32-rounded)
__device__ float g_w   [722048];              // tf32 weights: qkv(196608), fc1, fc2, bqkv

#define WOFF_QKV  0
#define WOFF_FC1  196608
#define WOFF_FC2  458752
#define WOFF_BQKV 720896

__device__ __forceinline__ unsigned f2tf32(float x) {
    unsigned u;
    asm("cvt.rna.tf32.f32 %0, %1;" : "=r"(u) : "f"(x));
    return u;
}
__device__ __forceinline__ float rtf32(float x) { return __uint_as_float(f2tf32(x)); }

// ---------------- weight prep ----------------
__global__ void round_copy_kernel(const float* __restrict__ src, float* __restrict__ dst, int n) {
    int i = (blockIdx.x * 256 + threadIdx.x) * 4;
    if (i < n) {
        float4 v = *(const float4*)&src[i];
        v.x = rtf32(v.x); v.y = rtf32(v.y); v.z = rtf32(v.z); v.w = rtf32(v.w);
        *(float4*)&dst[i] = v;
    }
}

// pack wq|wk|wv -> [256][768] tf32-rounded (4-elem runs never straddle a 256 boundary)
__global__ void pack_qkv_w_kernel(const float* __restrict__ wq, const float* __restrict__ wk,
                                  const float* __restrict__ wv, float* __restrict__ dst) {
    int i = (blockIdx.x * 256 + threadIdx.x) * 4;
    if (i < 256 * NQKV) {
        int kk = i / NQKV, n = i % NQKV;
        const float* src = (n < 256) ? &wq[kk * 256 + n]
                         : (n < 512) ? &wk[kk * 256 + n - 256]
                                     : &wv[kk * 256 + n - 512];
        float4 v = *(const float4*)src;
        v.x = rtf32(v.x); v.y = rtf32(v.y); v.z = rtf32(v.z); v.w = rtf32(v.w);
        *(float4*)&dst[i] = v;
    }
}

__global__ void pack_qkv_b_kernel(const float* __restrict__ bq, const float* __restrict__ bk,
                                  const float* __restrict__ bv, float* __restrict__ dst) {
    int n = blockIdx.x * 256 + threadIdx.x;
    if (n < NQKV)
        dst[n] = (n < 256) ? bq[n] : (n < 512) ? bk[n - 256] : bv[n - 512];
}

// ---------------- fused transpose-in + LN1 ----------------
// block: 32 positions x all 256 channels; writes xc [tok,C] and nbuf = tf32(LN1)
__global__ void __launch_bounds__(256) tln1_kernel(
        const float* __restrict__ x, const float* __restrict__ g, const float* __restrict__ b,
        float* __restrict__ xc, float* __restrict__ nbuf) {
    __shared__ float tile[256][33];
    int bb  = blockIdx.y;
    int p0  = blockIdx.x * 32;
    int tx  = threadIdx.x & 31, ty = threadIdx.x >> 5;   // 32 x 8

#pragma unroll
    for (int j = 0; j < 256; j += 8)
        tile[ty + j][tx] = x[((size_t)bb * CCH + ty + j) * HW + p0 + tx];
    __syncthreads();

    int warp = ty, lane = tx;
#pragma unroll
    for (int p = 0; p < 4; p++) {
        int pos = warp * 4 + p;
        float vv[8];
        float s = 0.0f, sq = 0.0f;
#pragma unroll
        for (int j = 0; j < 8; j++) {
            float f = tile[lane + 32 * j][pos];
            vv[j] = f; s += f; sq += f * f;
        }
#pragma unroll
        for (int off = 16; off > 0; off >>= 1) {
            s  += __shfl_xor_sync(0xffffffffu, s,  off);
            sq += __shfl_xor_sync(0xffffffffu, sq, off);
        }
        float mean = s * (1.0f / 256.0f);
        float var  = sq * (1.0f / 256.0f) - mean * mean;
        float inv  = rsqrtf(var + 1e-5f);
        size_t tok = (size_t)bb * HW + p0 + pos;
#pragma unroll
        for (int j = 0; j < 8; j++) {
            int c = lane + 32 * j;
            xc[tok * CCH + c]   = vv[j];
            nbuf[tok * CCH + c] = rtf32((vv[j] - mean) * inv * g[c] + b[c]);
        }
    }
}

// ---------------- 3-stage cp.async tf32 tensor-core GEMM ----------------
#define AS_STRIDE 36
#define BS_STRIDE 136
#define A_STAGE (128 * AS_STRIDE)
#define B_STAGE (32 * BS_STRIDE)
#define STAGE_F (A_STAGE + B_STAGE)
#define NSTAGE  3
#define GEMM_SMEM_BYTES (NSTAGE * STAGE_F * 4)

__device__ __forceinline__ void cp16(float* dst, const float* src) {
    unsigned d = (unsigned)__cvta_generic_to_shared(dst);
    asm volatile("cp.async.cg.shared.global [%0], [%1], 16;" :: "r"(d), "l"(src));
}

// EPI: 0 = bias store; 1 = bias+gelu, tf32-round; 2 = bias + residual + transpose store to [B,C,H,W]
template <int EPI>
__global__ void __launch_bounds__(256)
gemm_tf32_kernel(const float* __restrict__ A, const float* __restrict__ Bw,
                 const float* __restrict__ bias, float* __restrict__ Cout,
                 const float* __restrict__ resid, int K, int N) {
    extern __shared__ float sm[];
    int t    = threadIdx.x;
    int warp = t >> 5, lane = t & 31;
    int g    = lane >> 2;
    int tig  = lane & 3;
    int wm   = (warp >> 1) * 32;
    int wn   = (warp & 1) * 64;
    int bm   = blockIdx.y * 128;
    int bn   = blockIdx.x * 128;

    int aRow = t >> 3;
    int aC4  = (t & 7) * 4;
    int bRow = t >> 5;
    int bC4  = (t & 31) * 4;

    int nK = K >> 5;

    auto prefetch = [&](int s, int kb) {
        float* As = sm + s * STAGE_F;
        float* Bs = As + A_STAGE;
#pragma unroll
        for (int i = 0; i < 4; i++) {
            int row = aRow + 32 * i;
            cp16(&As[row * AS_STRIDE + aC4], &A[(size_t)(bm + row) * K + kb + aC4]);
        }
#pragma unroll
        for (int i = 0; i < 4; i++) {
            int row = bRow + 8 * i;
            cp16(&Bs[row * BS_STRIDE + bC4], &Bw[(size_t)(kb + row) * N + bn + bC4]);
        }
    };

    float c[2][8][4];
#pragma unroll
    for (int mf = 0; mf < 2; mf++)
#pragma unroll
        for (int nf = 0; nf < 8; nf++)
#pragma unroll
            for (int j = 0; j < 4; j++) c[mf][nf][j] = 0.0f;

    prefetch(0, 0);
    asm volatile("cp.async.commit_group;");
    prefetch(1, 32);
    asm volatile("cp.async.commit_group;");

    for (int kb = 0; kb < nK; kb++) {
        asm volatile("cp.async.wait_group 1;");
        __syncthreads();
        if (kb + 2 < nK) prefetch((kb + 2) % NSTAGE, (kb + 2) << 5);
        asm volatile("cp.async.commit_group;");

        const float* As = sm + (kb % NSTAGE) * STAGE_F;
        const float* Bs = As + A_STAGE;

#pragma unroll
        for (int ks = 0; ks < 4; ks++) {
            int k0 = ks * 8;
            unsigned a[2][4];
#pragma unroll
            for (int mf = 0; mf < 2; mf++) {
                int r0 = wm + mf * 16 + g;
                a[mf][0] = __float_as_uint(As[r0 * AS_STRIDE + k0 + tig]);
                a[mf][1] = __float_as_uint(As[(r0 + 8) * AS_STRIDE + k0 + tig]);
                a[mf][2] = __float_as_uint(As[r0 * AS_STRIDE + k0 + tig + 4]);
                a[mf][3] = __float_as_uint(As[(r0 + 8) * AS_STRIDE + k0 + tig + 4]);
            }
            unsigned b[8][2];
#pragma unroll
            for (int nf = 0; nf < 8; nf++) {
                int col = wn + nf * 8 + g;
                b[nf][0] = __float_as_uint(Bs[(k0 + tig) * BS_STRIDE + col]);
                b[nf][1] = __float_as_uint(Bs[(k0 + tig + 4) * BS_STRIDE + col]);
            }
#pragma unroll
            for (int mf = 0; mf < 2; mf++)
#pragma unroll
                for (int nf = 0; nf < 8; nf++) {
                    asm volatile(
                        "mma.sync.aligned.m16n8k8.row.col.f32.tf32.tf32.f32 "
                        "{%0,%1,%2,%3}, {%4,%5,%6,%7}, {%8,%9}, {%0,%1,%2,%3};"
                        : "+f"(c[mf][nf][0]), "+f"(c[mf][nf][1]),
                          "+f"(c[mf][nf][2]), "+f"(c[mf][nf][3])
                        : "r"(a[mf][0]), "r"(a[mf][1]), "r"(a[mf][2]), "r"(a[mf][3]),
                          "r"(b[nf][0]), "r"(b[nf][1]));
                }
        }
    }

#pragma unroll
    for (int mf = 0; mf < 2; mf++) {
        int row0 = bm + wm + mf * 16 + g;
#pragma unroll
        for (int nf = 0; nf < 8; nf++) {
            int col = bn + wn + nf * 8 + 2 * tig;
            float b0 = bias[col], b1 = bias[col + 1];
            float v0 = c[mf][nf][0] + b0;
            float v1 = c[mf][nf][1] + b1;
            float v2 = c[mf][nf][2] + b0;
            float v3 = c[mf][nf][3] + b1;
            if (EPI == 1) {
                v0 = rtf32(0.5f * v0 * (1.0f + erff(v0 * 0.70710678118654752f)));
                v1 = rtf32(0.5f * v1 * (1.0f + erff(v1 * 0.70710678118654752f)));
                v2 = rtf32(0.5f * v2 * (1.0f + erff(v2 * 0.70710678118654752f)));
                v3 = rtf32(0.5f * v3 * (1.0f + erff(v3 * 0.70710678118654752f)));
            }
            if (EPI == 2) {
                // residual + transpose store: Cout is out[B,C,H,W]
                float2 r0 = *(const float2*)&resid[(size_t)row0 * CCH + col];
                float2 r1 = *(const float2*)&resid[(size_t)(row0 + 8) * CCH + col];
                int bimg = row0 >> 14;
                int pos  = row0 & (HW - 1);
                size_t o0 = ((size_t)bimg * CCH + col) * HW + pos;
                size_t o1 = ((size_t)bimg * CCH + col + 1) * HW + pos;
                Cout[o0]     = v0 + r0.x;
                Cout[o1]     = v1 + r0.y;
                Cout[o0 + 8] = v2 + r1.x;
                Cout[o1 + 8] = v3 + r1.y;
            } else {
                *(float2*)&Cout[(size_t)row0 * N + col]       = make_float2(v0, v1);
                *(float2*)&Cout[(size_t)(row0 + 8) * N + col] = make_float2(v2, v3);
            }
        }
    }
}

// ---------------- attention + residual + fused LN2 ----------------
__global__ void __launch_bounds__(256) attn_ln2_kernel(
        const float* __restrict__ qkv, const float* __restrict__ xc,
        const float* __restrict__ lg, const float* __restrict__ lb,
        float* __restrict__ x1, float* __restrict__ nbuf) {
    int warp = threadIdx.x >> 5, lane = threadIdx.x & 31;
    size_t tok = (size_t)blockIdx.x * 8 + warp;
    int b = (int)(tok >> 14);
    int rem = (int)(tok & (HW - 1));
    int h = rem >> 7;
    int w = rem & 127;

    const float4* q4 = (const float4*)(qkv + tok * NQKV);
    float4 qa = q4[lane], qb = q4[lane + 32];

    float s[9];
#pragma unroll
    for (int n = 0; n < 9; n++) {
        int dy = n / 3 - 1, dx = n % 3 - 1;
        int hh = h + dy, ww = w + dx;
        bool valid = (hh >= 0) & (hh < HH) & (ww >= 0) & (ww < WWID);
        float part = 0.0f;
        if (valid) {
            size_t ntok = ((size_t)b * HW) + ((size_t)hh << 7) + ww;
            const float4* k4 = (const float4*)(qkv + ntok * NQKV + 256);
            float4 ka = k4[lane], kb = k4[lane + 32];
            part = qa.x * ka.x + qa.y * ka.y + qa.z * ka.z + qa.w * ka.w
                 + qb.x * kb.x + qb.y * kb.y + qb.z * kb.z + qb.w * kb.w;
        }
#pragma unroll
        for (int off = 16; off > 0; off >>= 1)
            part += __shfl_xor_sync(0xffffffffu, part, off);
        s[n] = valid ? part * 0.0625f : -1e30f;
    }

    float m = s[0];
#pragma unroll
    for (int n = 1; n < 9; n++) m = fmaxf(m, s[n]);
    float e[9], sum = 0.0f;
#pragma unroll
    for (int n = 0; n < 9; n++) { e[n] = (s[n] > -1e29f) ? expf(s[n] - m) : 0.0f; sum += e[n]; }
    float inv = 1.0f / sum;

    float4 acca = {0, 0, 0, 0}, accb = {0, 0, 0, 0};
#pragma unroll
    for (int n = 0; n < 9; n++) {
        if (e[n] > 0.0f) {
            float wn = e[n] * inv;
            int dy = n / 3 - 1, dx = n % 3 - 1;
            size_t ntok = ((size_t)b * HW) + ((size_t)(h + dy) << 7) + (w + dx);
            const float4* v4 = (const float4*)(qkv + ntok * NQKV + 512);
            float4 va = v4[lane], vb = v4[lane + 32];
            acca.x += wn * va.x; acca.y += wn * va.y; acca.z += wn * va.z; acca.w += wn * va.w;
            accb.x += wn * vb.x; accb.y += wn * vb.y; accb.z += wn * vb.z; accb.w += wn * vb.w;
        }
    }

    const float4* xc4 = (const float4*)(xc + tok * CCH);
    float4 ra = xc4[lane], rb = xc4[lane + 32];
    ra.x += acca.x; ra.y += acca.y; ra.z += acca.z; ra.w += acca.w;
    rb.x += accb.x; rb.y += accb.y; rb.z += accb.z; rb.w += accb.w;

    float4* o4 = (float4*)(x1 + tok * CCH);
    o4[lane] = ra;
    o4[lane + 32] = rb;

    // fused LN2 (warp holds all 256 channels)
    float ss = ra.x + ra.y + ra.z + ra.w + rb.x + rb.y + rb.z + rb.w;
    float sq = ra.x*ra.x + ra.y*ra.y + ra.z*ra.z + ra.w*ra.w
             + rb.x*rb.x + rb.y*rb.y + rb.z*rb.z + rb.w*rb.w;
#pragma unroll
    for (int off = 16; off > 0; off >>= 1) {
        ss += __shfl_xor_sync(0xffffffffu, ss, off);
        sq += __shfl_xor_sync(0xffffffffu, sq, off);
    }
    float mean = ss * (1.0f / 256.0f);
    float var  = sq * (1.0f / 256.0f) - mean * mean;
    float linv = rsqrtf(var + 1e-5f);

    const float4* g4 = (const float4*)lg;
    const float4* b4 = (const float4*)lb;
    float4* y4 = (float4*)(nbuf + tok * CCH);
    {
        float4 gg = g4[lane], bb2 = b4[lane], o;
        o.x = rtf32((ra.x - mean) * linv * gg.x + bb2.x);
        o.y = rtf32((ra.y - mean) * linv * gg.y + bb2.y);
        o.z = rtf32((ra.z - mean) * linv * gg.z + bb2.z);
        o.w = rtf32((ra.w - mean) * linv * gg.w + bb2.w);
        y4[lane] = o;
    }
    {
        float4 gg = g4[lane + 32], bb2 = b4[lane + 32], o;
        o.x = rtf32((rb.x - mean) * linv * gg.x + bb2.x);
        o.y = rtf32((rb.y - mean) * linv * gg.y + bb2.y);
        o.z = rtf32((rb.z - mean) * linv * gg.z + bb2.z);
        o.w = rtf32((rb.w - mean) * linv * gg.w + bb2.w);
        y4[lane + 32] = o;
    }
}

// ---------------- launch ----------------
extern "C" void kernel_launch(void* const* d_in, const int* in_sizes, int n_in,
                              void* d_out, int out_size) {
    const float* x     = (const float*)d_in[0];
    const float* wq    = (const float*)d_in[1];
    const float* bq    = (const float*)d_in[2];
    const float* wk    = (const float*)d_in[3];
    const float* bk    = (const float*)d_in[4];
    const float* wv    = (const float*)d_in[5];
    const float* bv    = (const float*)d_in[6];
    const float* ln1_g = (const float*)d_in[7];
    const float* ln1_b = (const float*)d_in[8];
    const float* ln2_g = (const float*)d_in[9];
    const float* ln2_b = (const float*)d_in[10];
    const float* fc1_w = (const float*)d_in[11];
    const float* fc1_b = (const float*)d_in[12];
    const float* fc2_w = (const float*)d_in[13];
    const float* fc2_b = (const float*)d_in[14];
    float* out = (float*)d_out;

    float *xc, *nbuf, *qkv, *x1, *hid, *wbuf;
    cudaGetSymbolAddress((void**)&xc,   g_xc);
    cudaGetSymbolAddress((void**)&nbuf, g_n);
    cudaGetSymbolAddress((void**)&qkv,  g_qkv);
    cudaGetSymbolAddress((void**)&x1,   g_x1);
    cudaGetSymbolAddress((void**)&hid,  g_hid);
    cudaGetSymbolAddress((void**)&wbuf, g_w);

    cudaFuncSetAttribute(gemm_tf32_kernel<0>,
                         cudaFuncAttributeMaxDynamicSharedMemorySize, GEMM_SMEM_BYTES);
    cudaFuncSetAttribute(gemm_tf32_kernel<1>,
                         cudaFuncAttributeMaxDynamicSharedMemorySize, GEMM_SMEM_BYTES);
    cudaFuncSetAttribute(gemm_tf32_kernel<2>,
                         cudaFuncAttributeMaxDynamicSharedMemorySize, GEMM_SMEM_BYTES);

    // weight prep (tf32 pre-round + QKV packing)
    pack_qkv_w_kernel<<<192, 256>>>(wq, wk, wv, wbuf + WOFF_QKV);
    pack_qkv_b_kernel<<<3,   256>>>(bq, bk, bv, wbuf + WOFF_BQKV);
    round_copy_kernel<<<256, 256>>>(fc1_w, wbuf + WOFF_FC1, 262144);
    round_copy_kernel<<<256, 256>>>(fc2_w, wbuf + WOFF_FC2, 262144);

    tln1_kernel<<<dim3(HW / 32, BB), 256>>>(x, ln1_g, ln1_b, xc, nbuf);
    gemm_tf32_kernel<0><<<dim3(NQKV / 128, NT / 128), 256, GEMM_SMEM_BYTES>>>(
        nbuf, wbuf + WOFF_QKV, wbuf + WOFF_BQKV, qkv, nullptr, 256, NQKV);
    attn_ln2_kernel<<<NT / 8, 256>>>(qkv, xc, ln2_g, ln2_b, x1, nbuf);
    gemm_tf32_kernel<1><<<dim3(HIDN / 128, NT / 128), 256, GEMM_SMEM_BYTES>>>(
        nbuf, wbuf + WOFF_FC1, fc1_b, hid, nullptr, 256, HIDN);
    gemm_tf32_kernel<2><<<dim3(CCH / 128, NT / 128), 256, GEMM_SMEM_BYTES>>>(
        hid, wbuf + WOFF_FC2, fc2_b, out, x1, HIDN, CCH);
}